// round 2
// baseline (speedup 1.0000x reference)
#include <cuda_runtime.h>

#define NN 100000
#define EE 1600000
#define FF 128
#define HH 64

// ---------------- device scratch (static; no runtime allocation) ------------
__device__ float g_bufA[NN * HH];
__device__ float g_bufB[NN * HH];
__device__ float g_bufC[NN * HH];
__device__ float g_bufD[NN * HH];
__device__ int   g_cnt[2 * NN];      // [0,NN): pri in-degree, [NN,2NN): sup
__device__ float g_dinv[3 * NN];     // [0]: pri eps=0.3, [1]: pri eps=0.5, [2]: sup eps=0.5

// ---------------- degree / norm ------------------------------------------------
__global__ void zero_cnt_kernel() {
    int i = blockIdx.x * blockDim.x + threadIdx.x;
    if (i < 2 * NN) g_cnt[i] = 0;
}

__global__ void count_kernel(const int* __restrict__ pri,
                             const int* __restrict__ sup) {
    int i = blockIdx.x * blockDim.x + threadIdx.x;
    if (i < EE) {
        atomicAdd(&g_cnt[pri[EE + i]], 1);
    } else if (i < 2 * EE) {
        atomicAdd(&g_cnt[NN + sup[i]], 1);   // sup col element (i-EE) -> sup[EE+(i-EE)] = sup[i]
    }
}

__global__ void dinv_kernel() {
    int i = blockIdx.x * blockDim.x + threadIdx.x;
    if (i >= NN) return;
    float cp = (float)g_cnt[i];
    float cs = (float)g_cnt[NN + i];
    g_dinv[i]          = rsqrtf(cp + 0.3f);
    g_dinv[NN + i]     = rsqrtf(cp + 0.5f);
    g_dinv[2 * NN + i] = rsqrtf(cs + 0.5f);
}

// ---------------- linear layer: out = x @ w^T + b ------------------------------
// block: 256 threads, 32 rows per block (100000 / 32 = 3125 exact).
__global__ void linear_kernel(const float* __restrict__ x,
                              const float* __restrict__ w,
                              const float* __restrict__ b,
                              float* __restrict__ out0,
                              float* __restrict__ out1) {
    __shared__ float xs[32][FF];       // 16 KB
    __shared__ float wt[FF][HH];       // 32 KB (transposed weights)
    int tid  = threadIdx.x;
    int row0 = blockIdx.x * 32;

    for (int i = tid; i < HH * FF; i += 256) {
        int k = i & (HH - 1);
        int f = i >> 6;
        wt[f][k] = w[k * FF + f];
    }
    for (int i = tid; i < 32 * FF; i += 256) {
        int r = i >> 7;
        int f = i & (FF - 1);
        xs[r][f] = x[(long long)(row0 + r) * FF + f];
    }
    __syncthreads();

    int k0 = (tid & 15) * 4;
    int r0 = (tid >> 4) * 2;

    float acc0[4], acc1[4];
#pragma unroll
    for (int j = 0; j < 4; j++) { acc0[j] = b[k0 + j]; acc1[j] = acc0[j]; }

#pragma unroll 4
    for (int f = 0; f < FF; f++) {
        float4 wv = *reinterpret_cast<const float4*>(&wt[f][k0]);
        float xv0 = xs[r0][f];
        float xv1 = xs[r0 + 1][f];
        acc0[0] += xv0 * wv.x; acc0[1] += xv0 * wv.y;
        acc0[2] += xv0 * wv.z; acc0[3] += xv0 * wv.w;
        acc1[0] += xv1 * wv.x; acc1[1] += xv1 * wv.y;
        acc1[2] += xv1 * wv.z; acc1[3] += xv1 * wv.w;
    }

    long long o0 = (long long)(row0 + r0) * HH + k0;
    long long o1 = o0 + HH;
    float4 v0 = make_float4(acc0[0], acc0[1], acc0[2], acc0[3]);
    float4 v1 = make_float4(acc1[0], acc1[1], acc1[2], acc1[3]);
    *reinterpret_cast<float4*>(out0 + o0) = v0;
    *reinterpret_cast<float4*>(out0 + o1) = v1;
    if (out1) {
        *reinterpret_cast<float4*>(out1 + o0) = v0;
        *reinterpret_cast<float4*>(out1 + o1) = v1;
    }
}

// ---------------- propagation: init (self-loop + residual, optional add) ------
// out[c,:] = ((1-eps) + eps*dinv[c]^2) * h[c,:]  (+ add[c,:])
__global__ void init_scale_kernel(const float* __restrict__ h,
                                  const float* __restrict__ dinv,
                                  float eps,
                                  const float* __restrict__ add,
                                  float* __restrict__ out) {
    int i = blockIdx.x * blockDim.x + threadIdx.x;   // float4 index, NN*16 total
    if (i >= NN * (HH / 4)) return;
    int c = i >> 4;
    float d = dinv[c];
    float s = (1.0f - eps) + eps * d * d;
    float4 v = reinterpret_cast<const float4*>(h)[i];
    v.x *= s; v.y *= s; v.z *= s; v.w *= s;
    if (add) {
        float4 a = reinterpret_cast<const float4*>(add)[i];
        v.x += a.x; v.y += a.y; v.z += a.z; v.w += a.w;
    }
    reinterpret_cast<float4*>(out)[i] = v;
}

// ---------------- propagation: edge scatter ------------------------------------
// 16 threads per edge; each moves one float4 (row of 64 floats = 16 x float4).
// out[c,:] += dinv[r]*dinv[c] * h[r,:]
__global__ void scatter_kernel(const int* __restrict__ edges,
                               const float* __restrict__ dinv,
                               const float* __restrict__ h,
                               float* __restrict__ out) {
    int t = blockIdx.x * blockDim.x + threadIdx.x;
    int e = t >> 4;
    if (e >= EE) return;
    int lane = t & 15;

    int r = edges[e];
    int c = edges[EE + e];
    float coef = dinv[r] * dinv[c];

    float4 v = reinterpret_cast<const float4*>(h + (long long)r * HH)[lane];
    v.x *= coef; v.y *= coef; v.z *= coef; v.w *= coef;

    float* dst = out + (long long)c * HH + lane * 4;
    asm volatile("red.global.add.v4.f32 [%0], {%1, %2, %3, %4};"
                 :: "l"(dst), "f"(v.x), "f"(v.y), "f"(v.z), "f"(v.w)
                 : "memory");
}

// ---------------- launch --------------------------------------------------------
extern "C" void kernel_launch(void* const* d_in, const int* in_sizes, int n_in,
                              void* d_out, int out_size) {
    const float* x   = (const float*)d_in[0];
    const int*   pri = (const int*)d_in[1];
    const int*   sup = (const int*)d_in[2];
    const float* w1  = (const float*)d_in[3];
    const float* b1  = (const float*)d_in[4];
    const float* w2  = (const float*)d_in[5];
    const float* b2  = (const float*)d_in[6];
    float* out = (float*)d_out;

    float *bufA, *bufB, *bufC, *bufD, *dinv;
    cudaGetSymbolAddress((void**)&bufA, g_bufA);
    cudaGetSymbolAddress((void**)&bufB, g_bufB);
    cudaGetSymbolAddress((void**)&bufC, g_bufC);
    cudaGetSymbolAddress((void**)&bufD, g_bufD);
    cudaGetSymbolAddress((void**)&dinv, g_dinv);
    const float* dinv_p1 = dinv;             // pri, eps=0.3
    const float* dinv_p2 = dinv + NN;        // pri, eps=0.5
    const float* dinv_s  = dinv + 2 * NN;    // sup, eps=0.5

    const int TPB = 256;
    const int gridCnt   = (2 * EE + TPB - 1) / TPB;
    const int gridNode  = (NN + TPB - 1) / TPB;
    const int gridLin   = NN / 32;                    // 3125, exact
    const int gridInit  = (NN * (HH / 4) + TPB - 1) / TPB;
    const int gridScat  = (EE * 16 + TPB - 1) / TPB;  // 100000

    // degrees + norms
    zero_cnt_kernel<<<(2 * NN + TPB - 1) / TPB, TPB>>>();
    count_kernel<<<gridCnt, TPB>>>(pri, sup);
    dinv_kernel<<<gridNode, TPB>>>();

    // linear layers: h1 -> bufA ; h2 -> bufC and bufD
    linear_kernel<<<gridLin, TPB>>>(x, w1, b1, bufA, nullptr);
    linear_kernel<<<gridLin, TPB>>>(x, w2, b2, bufC, bufD);

    float* z1 = out;
    float* z2 = out + (long long)NN * HH;

    // z1: pri, eps=0.3, 2 hops: bufA -> bufB -> z1
    init_scale_kernel<<<gridInit, TPB>>>(bufA, dinv_p1, 0.3f, nullptr, bufB);
    scatter_kernel<<<gridScat, TPB>>>(pri, dinv_p1, bufA, bufB);
    init_scale_kernel<<<gridInit, TPB>>>(bufB, dinv_p1, 0.3f, nullptr, z1);
    scatter_kernel<<<gridScat, TPB>>>(pri, dinv_p1, bufB, z1);

    // z2 part 1: sup, eps=0.5, 2 hops: bufC -> bufA -> bufB
    init_scale_kernel<<<gridInit, TPB>>>(bufC, dinv_s, 0.5f, nullptr, bufA);
    scatter_kernel<<<gridScat, TPB>>>(sup, dinv_s, bufC, bufA);
    init_scale_kernel<<<gridInit, TPB>>>(bufA, dinv_s, 0.5f, nullptr, bufB);
    scatter_kernel<<<gridScat, TPB>>>(sup, dinv_s, bufA, bufB);

    // z2 part 2: pri, eps=0.5, 2 hops: bufD -> bufC -> z2 (+ bufB folded in)
    init_scale_kernel<<<gridInit, TPB>>>(bufD, dinv_p2, 0.5f, nullptr, bufC);
    scatter_kernel<<<gridScat, TPB>>>(pri, dinv_p2, bufD, bufC);
    init_scale_kernel<<<gridInit, TPB>>>(bufC, dinv_p2, 0.5f, bufB, z2);
    scatter_kernel<<<gridScat, TPB>>>(pri, dinv_p2, bufC, z2);
}

// round 3
// speedup vs baseline: 1.9452x; 1.9452x over previous
#include <cuda_runtime.h>

#define NN 100000
#define EE 1600000
#define FF 128
#define HH 64

#define SCAN_B 1024
#define NBLK ((NN + SCAN_B - 1) / SCAN_B)   // 98

// ---------------- device scratch (static; no runtime allocation) ------------
__device__ float g_bufA[NN * HH];
__device__ float g_bufB[NN * HH];
__device__ float g_bufC[NN * HH];
__device__ int   g_cnt[2 * NN];       // in-degree: [0,NN) pri, [NN,2NN) sup
__device__ float g_dinv[3 * NN];      // [0]: pri eps=0.3, [1]: pri eps=0.5, [2]: sup eps=0.5
__device__ int   g_rowptr[2 * NN];    // CSR starts (by col): pri, sup
__device__ int   g_cursor[2 * NN];
__device__ int   g_bsum[2 * NBLK];
__device__ int   g_boff[2 * NBLK];
__device__ int   g_srcsort[2 * EE];   // src node ids sorted by col: pri @0, sup @EE

// ---------------- degree -------------------------------------------------------
__global__ void zero_cnt_kernel() {
    int i = blockIdx.x * blockDim.x + threadIdx.x;
    if (i < 2 * NN) g_cnt[i] = 0;
}

__global__ void count_kernel(const int* __restrict__ pri,
                             const int* __restrict__ sup) {
    int i = blockIdx.x * blockDim.x + threadIdx.x;
    if (i < EE) {
        atomicAdd(&g_cnt[pri[EE + i]], 1);
    } else if (i < 2 * EE) {
        atomicAdd(&g_cnt[NN + sup[i]], 1);
    }
}

__global__ void dinv_kernel() {
    int i = blockIdx.x * blockDim.x + threadIdx.x;
    if (i >= NN) return;
    float cp = (float)g_cnt[i];
    float cs = (float)g_cnt[NN + i];
    g_dinv[i]          = rsqrtf(cp + 0.3f);
    g_dinv[NN + i]     = rsqrtf(cp + 0.5f);
    g_dinv[2 * NN + i] = rsqrtf(cs + 0.5f);
}

// ---------------- exclusive scan of degrees -> CSR rowptr ----------------------
__global__ void scan1_kernel() {   // grid (NBLK, 2), block SCAN_B
    __shared__ int sh[SCAN_B];
    int seg = blockIdx.y;
    int i = blockIdx.x * SCAN_B + threadIdx.x;
    int v = (i < NN) ? g_cnt[seg * NN + i] : 0;
    sh[threadIdx.x] = v;
    __syncthreads();
    for (int off = 1; off < SCAN_B; off <<= 1) {
        int t = (threadIdx.x >= off) ? sh[threadIdx.x - off] : 0;
        __syncthreads();
        sh[threadIdx.x] += t;
        __syncthreads();
    }
    if (i < NN) g_rowptr[seg * NN + i] = sh[threadIdx.x] - v;   // exclusive
    if (threadIdx.x == SCAN_B - 1) g_bsum[seg * NBLK + blockIdx.x] = sh[threadIdx.x];
}

__global__ void scan2_kernel() {   // grid (1, 2), block 128
    __shared__ int sh[NBLK];
    int seg = blockIdx.y;
    if (threadIdx.x < NBLK) sh[threadIdx.x] = g_bsum[seg * NBLK + threadIdx.x];
    __syncthreads();
    if (threadIdx.x == 0) {
        int run = 0;
        for (int j = 0; j < NBLK; j++) { int t = sh[j]; sh[j] = run; run += t; }
    }
    __syncthreads();
    if (threadIdx.x < NBLK) g_boff[seg * NBLK + threadIdx.x] = sh[threadIdx.x];
}

__global__ void scan3_kernel() {   // grid (NBLK, 2), block SCAN_B
    int seg = blockIdx.y;
    int i = blockIdx.x * SCAN_B + threadIdx.x;
    if (i < NN) {
        g_rowptr[seg * NN + i] += g_boff[seg * NBLK + blockIdx.x];
        g_cursor[seg * NN + i] = 0;
    }
}

__global__ void fill_kernel(const int* __restrict__ pri,
                            const int* __restrict__ sup) {
    int i = blockIdx.x * blockDim.x + threadIdx.x;
    if (i < EE) {
        int r = pri[i], c = pri[EE + i];
        int pos = g_rowptr[c] + atomicAdd(&g_cursor[c], 1);
        g_srcsort[pos] = r;
    } else if (i < 2 * EE) {
        int e = i - EE;
        int r = sup[e], c = sup[EE + e];
        int pos = g_rowptr[NN + c] + atomicAdd(&g_cursor[NN + c], 1);
        g_srcsort[EE + pos] = r;
    }
}

// ---------------- fused linear: out = x @ w^T + b ------------------------------
// one thread per row; 64 register accumulators; w transposed in smem, read by
// warp-uniform broadcast (conflict-free). blockIdx.y: 0 -> (w1,b1,bufA),
// 1 -> (w2,b2,bufC).
__global__ void linear_kernel(const float* __restrict__ x,
                              const float* __restrict__ w1,
                              const float* __restrict__ b1,
                              const float* __restrict__ w2,
                              const float* __restrict__ b2,
                              float* __restrict__ o1,
                              float* __restrict__ o2) {
    __shared__ float wt[FF][HH];   // 32 KB, [f][k]
    __shared__ float bs[HH];
    const float* w = blockIdx.y ? w2 : w1;
    const float* b = blockIdx.y ? b2 : b1;
    float* outp    = blockIdx.y ? o2 : o1;

    int tid = threadIdx.x;
    for (int i = tid; i < HH * FF; i += 256) {
        int k = i & (HH - 1);
        int f = i >> 6;
        wt[f][k] = w[k * FF + f];
    }
    if (tid < HH) bs[tid] = b[tid];
    __syncthreads();

    int row = blockIdx.x * 256 + tid;
    if (row >= NN) return;

    float acc[HH];
#pragma unroll
    for (int k = 0; k < HH; k++) acc[k] = bs[k];

    const float4* xr = reinterpret_cast<const float4*>(x + (size_t)row * FF);
#pragma unroll 4
    for (int f4 = 0; f4 < FF / 4; f4++) {
        float4 xv = xr[f4];
        float xq[4] = {xv.x, xv.y, xv.z, xv.w};
#pragma unroll
        for (int q = 0; q < 4; q++) {
            int f = f4 * 4 + q;
            float xs_ = xq[q];
#pragma unroll
            for (int k4 = 0; k4 < HH / 4; k4++) {
                float4 wv = *reinterpret_cast<const float4*>(&wt[f][k4 * 4]);
                acc[k4 * 4 + 0] += xs_ * wv.x;
                acc[k4 * 4 + 1] += xs_ * wv.y;
                acc[k4 * 4 + 2] += xs_ * wv.z;
                acc[k4 * 4 + 3] += xs_ * wv.w;
            }
        }
    }

    float4* op = reinterpret_cast<float4*>(outp + (size_t)row * HH);
#pragma unroll
    for (int k4 = 0; k4 < HH / 4; k4++)
        op[k4] = make_float4(acc[k4 * 4], acc[k4 * 4 + 1], acc[k4 * 4 + 2], acc[k4 * 4 + 3]);
}

// ---------------- fused gather hop ---------------------------------------------
// out[c,:] = ((1-eps)+eps*dinv[c]^2) * h[c,:] + sum_{r->c} dinv[r]*dinv[c]*h[r,:] (+ add)
// one warp per node; each lane owns 2 floats of the 64-float row.
__global__ void hop_kernel(const int* __restrict__ srcs,
                           const int* __restrict__ rowptr,
                           const int* __restrict__ cnt,
                           const float* __restrict__ dinv,
                           float eps,
                           const float* __restrict__ h,
                           const float* __restrict__ add,
                           float* __restrict__ out) {
    int warp = (blockIdx.x * blockDim.x + threadIdx.x) >> 5;
    if (warp >= NN) return;
    int lane = threadIdx.x & 31;
    int c = warp;

    float dc = dinv[c];
    float s = (1.0f - eps) + eps * dc * dc;

    float2 acc = reinterpret_cast<const float2*>(h + (size_t)c * HH)[lane];
    acc.x *= s; acc.y *= s;

    int start = rowptr[c];
    int n = cnt[c];
    for (int base = 0; base < n; base += 32) {
        int m = n - base; if (m > 32) m = 32;
        int r = 0; float dr = 0.0f;
        if (lane < m) {
            r = srcs[start + base + lane];
            dr = dinv[r];
        }
#pragma unroll 4
        for (int j = 0; j < m; j++) {
            int   rj = __shfl_sync(0xffffffffu, r, j);
            float cf = __shfl_sync(0xffffffffu, dr, j) * dc;
            float2 v = reinterpret_cast<const float2*>(h + (size_t)rj * HH)[lane];
            acc.x += cf * v.x;
            acc.y += cf * v.y;
        }
    }

    if (add) {
        float2 a = reinterpret_cast<const float2*>(add + (size_t)c * HH)[lane];
        acc.x += a.x; acc.y += a.y;
    }
    reinterpret_cast<float2*>(out + (size_t)c * HH)[lane] = acc;
}

// ---------------- launch --------------------------------------------------------
extern "C" void kernel_launch(void* const* d_in, const int* in_sizes, int n_in,
                              void* d_out, int out_size) {
    const float* x   = (const float*)d_in[0];
    const int*   pri = (const int*)d_in[1];
    const int*   sup = (const int*)d_in[2];
    const float* w1  = (const float*)d_in[3];
    const float* b1  = (const float*)d_in[4];
    const float* w2  = (const float*)d_in[5];
    const float* b2  = (const float*)d_in[6];
    float* out = (float*)d_out;

    float *bufA, *bufB, *bufC, *dinv;
    int *cnt, *rowptr, *srcsort;
    cudaGetSymbolAddress((void**)&bufA, g_bufA);
    cudaGetSymbolAddress((void**)&bufB, g_bufB);
    cudaGetSymbolAddress((void**)&bufC, g_bufC);
    cudaGetSymbolAddress((void**)&dinv, g_dinv);
    cudaGetSymbolAddress((void**)&cnt, g_cnt);
    cudaGetSymbolAddress((void**)&rowptr, g_rowptr);
    cudaGetSymbolAddress((void**)&srcsort, g_srcsort);

    const float* dinv_p1 = dinv;             // pri, eps=0.3
    const float* dinv_p2 = dinv + NN;        // pri, eps=0.5
    const float* dinv_s  = dinv + 2 * NN;    // sup, eps=0.5

    const int TPB = 256;
    const int gridCnt  = (2 * EE + TPB - 1) / TPB;
    const int gridNode = (NN + TPB - 1) / TPB;
    const int gridHop  = (NN * 32 + TPB - 1) / TPB;   // one warp per node

    // degrees + norms + CSR build
    zero_cnt_kernel<<<(2 * NN + TPB - 1) / TPB, TPB>>>();
    count_kernel<<<gridCnt, TPB>>>(pri, sup);
    dinv_kernel<<<gridNode, TPB>>>();
    scan1_kernel<<<dim3(NBLK, 2), SCAN_B>>>();
    scan2_kernel<<<dim3(1, 2), 128>>>();
    scan3_kernel<<<dim3(NBLK, 2), SCAN_B>>>();
    fill_kernel<<<gridCnt, TPB>>>(pri, sup);

    // fused linear layers: h1 -> bufA ; h2 -> bufC
    linear_kernel<<<dim3((NN + 255) / 256, 2), 256>>>(x, w1, b1, w2, b2, bufA, bufC);

    float* z1 = out;
    float* z2 = out + (size_t)NN * HH;

    const int* pri_src = srcsort;
    const int* sup_src = srcsort + EE;
    const int* pri_rp  = rowptr;
    const int* sup_rp  = rowptr + NN;
    const int* pri_cnt = cnt;
    const int* sup_cnt = cnt + NN;

    // z1: pri, eps=0.3, 2 hops: bufA -> bufB -> z1
    hop_kernel<<<gridHop, TPB>>>(pri_src, pri_rp, pri_cnt, dinv_p1, 0.3f, bufA, nullptr, bufB);
    hop_kernel<<<gridHop, TPB>>>(pri_src, pri_rp, pri_cnt, dinv_p1, 0.3f, bufB, nullptr, z1);

    // z2 sup chain: bufC -> bufA -> bufB
    hop_kernel<<<gridHop, TPB>>>(sup_src, sup_rp, sup_cnt, dinv_s, 0.5f, bufC, nullptr, bufA);
    hop_kernel<<<gridHop, TPB>>>(sup_src, sup_rp, sup_cnt, dinv_s, 0.5f, bufA, nullptr, bufB);

    // z2 pri chain: bufC -> bufA -> z2 (+ bufB folded into final hop)
    hop_kernel<<<gridHop, TPB>>>(pri_src, pri_rp, pri_cnt, dinv_p2, 0.5f, bufC, nullptr, bufA);
    hop_kernel<<<gridHop, TPB>>>(pri_src, pri_rp, pri_cnt, dinv_p2, 0.5f, bufA, bufB, z2);
}

// round 5
// speedup vs baseline: 1.9769x; 1.0163x over previous
#include <cuda_runtime.h>
#include <cuda_fp16.h>

#define NN 100000
#define EE 1600000
#define FF 128
#define HH 64
#define H2 (HH / 2)      // 32 half2 per row

#define SCAN_B 1024
#define NBLK ((NN + SCAN_B - 1) / SCAN_B)   // 98

// ---------------- device scratch (static; no runtime allocation) ------------
__device__ __half2 g_bufA[NN * H2];
__device__ __half2 g_bufB[NN * H2];
__device__ __half2 g_bufC[NN * H2];
__device__ int     g_cnt[2 * NN];      // in-degree: [0,NN) pri, [NN,2NN) sup
__device__ float   g_dinv[3 * NN];     // [0]: pri eps=0.3, [1]: pri eps=0.5, [2]: sup eps=0.5
__device__ int     g_rowptr[2 * NN];   // CSR starts (by col): pri, sup
__device__ int     g_cursor[2 * NN];
__device__ int     g_bsum[2 * NBLK];
__device__ int     g_boff[2 * NBLK];
__device__ int2    g_pri_pack[EE];     // {src, f32 bits of dinv_p1[src]}
__device__ float   g_pri_c2[EE];       // dinv_p2[src], same order
__device__ int2    g_sup_pack[EE];     // {src, f32 bits of dinv_s[src]}

// ---------------- degree -------------------------------------------------------
__global__ void zero_cnt_kernel() {
    int i = blockIdx.x * blockDim.x + threadIdx.x;
    if (i < 2 * NN) g_cnt[i] = 0;
}

__global__ void count_kernel(const int* __restrict__ pri,
                             const int* __restrict__ sup) {
    int i = blockIdx.x * blockDim.x + threadIdx.x;
    if (i < EE) {
        atomicAdd(&g_cnt[pri[EE + i]], 1);
    } else if (i < 2 * EE) {
        atomicAdd(&g_cnt[NN + sup[i]], 1);   // sup col element (i-EE)
    }
}

__global__ void dinv_kernel() {
    int i = blockIdx.x * blockDim.x + threadIdx.x;
    if (i >= NN) return;
    float cp = (float)g_cnt[i];
    float cs = (float)g_cnt[NN + i];
    g_dinv[i]          = rsqrtf(cp + 0.3f);
    g_dinv[NN + i]     = rsqrtf(cp + 0.5f);
    g_dinv[2 * NN + i] = rsqrtf(cs + 0.5f);
}

// ---------------- exclusive scan of degrees -> CSR rowptr ----------------------
__global__ void scan1_kernel() {   // grid (NBLK, 2), block SCAN_B
    __shared__ int sh[SCAN_B];
    int seg = blockIdx.y;
    int i = blockIdx.x * SCAN_B + threadIdx.x;
    int v = (i < NN) ? g_cnt[seg * NN + i] : 0;
    sh[threadIdx.x] = v;
    __syncthreads();
    for (int off = 1; off < SCAN_B; off <<= 1) {
        int t = (threadIdx.x >= off) ? sh[threadIdx.x - off] : 0;
        __syncthreads();
        sh[threadIdx.x] += t;
        __syncthreads();
    }
    if (i < NN) g_rowptr[seg * NN + i] = sh[threadIdx.x] - v;   // exclusive
    if (threadIdx.x == SCAN_B - 1) g_bsum[seg * NBLK + blockIdx.x] = sh[threadIdx.x];
}

__global__ void scan2_kernel() {   // grid (1, 2), block 128
    __shared__ int sh[NBLK];
    int seg = blockIdx.y;
    if (threadIdx.x < NBLK) sh[threadIdx.x] = g_bsum[seg * NBLK + threadIdx.x];
    __syncthreads();
    if (threadIdx.x == 0) {
        int run = 0;
        for (int j = 0; j < NBLK; j++) { int t = sh[j]; sh[j] = run; run += t; }
    }
    __syncthreads();
    if (threadIdx.x < NBLK) g_boff[seg * NBLK + threadIdx.x] = sh[threadIdx.x];
}

__global__ void scan3_kernel() {   // grid (NBLK, 2), block SCAN_B
    int seg = blockIdx.y;
    int i = blockIdx.x * SCAN_B + threadIdx.x;
    if (i < NN) {
        int rp = g_rowptr[seg * NN + i] + g_boff[seg * NBLK + blockIdx.x];
        g_rowptr[seg * NN + i] = rp;
        g_cursor[seg * NN + i] = rp;     // cursor starts at rowptr
    }
}

// fill: write {src, dinv[src]} sorted by col. One atomic per edge.
__global__ void fill_kernel(const int* __restrict__ pri,
                            const int* __restrict__ sup) {
    int i = blockIdx.x * blockDim.x + threadIdx.x;
    if (i < EE) {
        int r = pri[i], c = pri[EE + i];
        int pos = atomicAdd(&g_cursor[c], 1);
        g_pri_pack[pos] = make_int2(r, __float_as_int(g_dinv[r]));
        g_pri_c2[pos]   = g_dinv[NN + r];
    } else if (i < 2 * EE) {
        int e = i - EE;
        int r = sup[e], c = sup[EE + e];
        int pos = atomicAdd(&g_cursor[NN + c], 1);   // seg-relative, in [0,EE)
        g_sup_pack[pos] = make_int2(r, __float_as_int(g_dinv[2 * NN + r]));
    }
}

// ---------------- fused linear: out = x @ w^T + b  (fp16 output) ---------------
// one thread per row; 64 register accumulators; w transposed in smem, read by
// warp-uniform broadcast. blockIdx.y: 0 -> (w1,b1,oA), 1 -> (w2,b2,oC).
__global__ void linear_kernel(const float* __restrict__ x,
                              const float* __restrict__ w1,
                              const float* __restrict__ b1,
                              const float* __restrict__ w2,
                              const float* __restrict__ b2,
                              __half2* __restrict__ o1,
                              __half2* __restrict__ o2) {
    __shared__ float wt[FF][HH];   // 32 KB, [f][k]
    __shared__ float bs[HH];
    const float* w   = blockIdx.y ? w2 : w1;
    const float* b   = blockIdx.y ? b2 : b1;
    __half2* outp    = blockIdx.y ? o2 : o1;

    int tid = threadIdx.x;
    for (int i = tid; i < HH * FF; i += 256) {
        int k = i & (HH - 1);
        int f = i >> 6;
        wt[f][k] = w[k * FF + f];
    }
    if (tid < HH) bs[tid] = b[tid];
    __syncthreads();

    int row = blockIdx.x * 256 + tid;
    if (row >= NN) return;

    float acc[HH];
#pragma unroll
    for (int k = 0; k < HH; k++) acc[k] = bs[k];

    const float4* xr = reinterpret_cast<const float4*>(x + (size_t)row * FF);
#pragma unroll 4
    for (int f4 = 0; f4 < FF / 4; f4++) {
        float4 xv = xr[f4];
        float xq[4] = {xv.x, xv.y, xv.z, xv.w};
#pragma unroll
        for (int q = 0; q < 4; q++) {
            int f = f4 * 4 + q;
            float xs_ = xq[q];
#pragma unroll
            for (int k4 = 0; k4 < HH / 4; k4++) {
                float4 wv = *reinterpret_cast<const float4*>(&wt[f][k4 * 4]);
                acc[k4 * 4 + 0] += xs_ * wv.x;
                acc[k4 * 4 + 1] += xs_ * wv.y;
                acc[k4 * 4 + 2] += xs_ * wv.z;
                acc[k4 * 4 + 3] += xs_ * wv.w;
            }
        }
    }

    // pack to half2 and write the FULL 128-byte row as 8 x uint4 (union: no UB)
    union Pack {
        __half2 h2[H2];        // 32 half2 = 128 B
        uint4   u4[H2 / 4];    // 8 uint4  = 128 B
    } p;
#pragma unroll
    for (int k2 = 0; k2 < H2; k2++)
        p.h2[k2] = __floats2half2_rn(acc[2 * k2], acc[2 * k2 + 1]);
    uint4* op = reinterpret_cast<uint4*>(outp + (size_t)row * H2);
#pragma unroll
    for (int q = 0; q < H2 / 4; q++) op[q] = p.u4[q];
}

// ---------------- fused gather hop ---------------------------------------------
// out[c,:] = ((1-eps)+eps*dc^2) * h[c,:] + sum_{r->c} dr*dc*h[r,:]  (+ add)
// one warp per node; each lane owns one half2 (2 floats) of the row.
// C2: coefficient comes from the parallel fp32 array (pri @ eps=0.5).
// FINAL: write fp32 to out (float2), optionally folding in `add` (half2).
template <bool C2, bool FINAL>
__global__ void hop_kernel(const int2* __restrict__ pack,
                           const float* __restrict__ c2,
                           const int* __restrict__ rowptr,
                           const int* __restrict__ cnt,
                           const float* __restrict__ dinv,
                           float eps,
                           const __half2* __restrict__ h,
                           const __half2* __restrict__ add,
                           void* __restrict__ out) {
    int warp = (blockIdx.x * blockDim.x + threadIdx.x) >> 5;
    if (warp >= NN) return;
    int lane = threadIdx.x & 31;
    int c = warp;

    float dc = dinv[c];
    float s = (1.0f - eps) + eps * dc * dc;

    float2 acc = __half22float2(h[(size_t)c * H2 + lane]);
    acc.x *= s; acc.y *= s;

    int start = rowptr[c];
    int n = cnt[c];
    for (int base = 0; base < n; base += 32) {
        int m = n - base; if (m > 32) m = 32;
        int2 e = make_int2(0, 0);
        float cv = 0.0f;
        if (lane < m) {
            e = pack[start + base + lane];
            if (C2) cv = c2[start + base + lane];
        }
#pragma unroll 4
        for (int j = 0; j < m; j++) {
            int   rj = __shfl_sync(0xffffffffu, e.x, j);
            float dr = C2 ? __shfl_sync(0xffffffffu, cv, j)
                          : __int_as_float(__shfl_sync(0xffffffffu, e.y, j));
            float cf = dr * dc;
            float2 v = __half22float2(h[(size_t)rj * H2 + lane]);
            acc.x += cf * v.x;
            acc.y += cf * v.y;
        }
    }

    if (FINAL) {
        if (add) {
            float2 a = __half22float2(add[(size_t)c * H2 + lane]);
            acc.x += a.x; acc.y += a.y;
        }
        reinterpret_cast<float2*>(out)[(size_t)c * H2 + lane] = acc;
    } else {
        reinterpret_cast<__half2*>(out)[(size_t)c * H2 + lane] = __float22half2_rn(acc);
    }
}

// ---------------- launch --------------------------------------------------------
extern "C" void kernel_launch(void* const* d_in, const int* in_sizes, int n_in,
                              void* d_out, int out_size) {
    const float* x   = (const float*)d_in[0];
    const int*   pri = (const int*)d_in[1];
    const int*   sup = (const int*)d_in[2];
    const float* w1  = (const float*)d_in[3];
    const float* b1  = (const float*)d_in[4];
    const float* w2  = (const float*)d_in[5];
    const float* b2  = (const float*)d_in[6];
    float* out = (float*)d_out;

    __half2 *bufA, *bufB, *bufC;
    float *dinv, *pri_c2;
    int *cnt, *rowptr;
    int2 *pri_pack, *sup_pack;
    cudaGetSymbolAddress((void**)&bufA, g_bufA);
    cudaGetSymbolAddress((void**)&bufB, g_bufB);
    cudaGetSymbolAddress((void**)&bufC, g_bufC);
    cudaGetSymbolAddress((void**)&dinv, g_dinv);
    cudaGetSymbolAddress((void**)&cnt, g_cnt);
    cudaGetSymbolAddress((void**)&rowptr, g_rowptr);
    cudaGetSymbolAddress((void**)&pri_pack, g_pri_pack);
    cudaGetSymbolAddress((void**)&sup_pack, g_sup_pack);
    cudaGetSymbolAddress((void**)&pri_c2, g_pri_c2);

    const float* dinv_p1 = dinv;             // pri, eps=0.3
    const float* dinv_p2 = dinv + NN;        // pri, eps=0.5
    const float* dinv_s  = dinv + 2 * NN;    // sup, eps=0.5

    const int TPB = 256;
    const int gridCnt  = (2 * EE + TPB - 1) / TPB;
    const int gridNode = (NN + TPB - 1) / TPB;
    const int gridHop  = (NN * 32 + TPB - 1) / TPB;   // one warp per node

    // degrees + norms + CSR build
    zero_cnt_kernel<<<(2 * NN + TPB - 1) / TPB, TPB>>>();
    count_kernel<<<gridCnt, TPB>>>(pri, sup);
    dinv_kernel<<<gridNode, TPB>>>();
    scan1_kernel<<<dim3(NBLK, 2), SCAN_B>>>();
    scan2_kernel<<<dim3(1, 2), 128>>>();
    scan3_kernel<<<dim3(NBLK, 2), SCAN_B>>>();
    fill_kernel<<<gridCnt, TPB>>>(pri, sup);

    // fused linear layers: h1 -> bufA ; h2 -> bufC (fp16)
    linear_kernel<<<dim3((NN + 255) / 256, 2), 256>>>(x, w1, b1, w2, b2, bufA, bufC);

    float2* z1 = reinterpret_cast<float2*>(out);
    float2* z2 = reinterpret_cast<float2*>(out + (size_t)NN * HH);

    const int* pri_rp  = rowptr;
    const int* sup_rp  = rowptr + NN;
    const int* pri_cnt = cnt;
    const int* sup_cnt = cnt + NN;

    // z1: pri, eps=0.3, 2 hops: bufA -> bufB -> z1 (fp32)
    hop_kernel<false, false><<<gridHop, TPB>>>(pri_pack, nullptr, pri_rp, pri_cnt,
                                               dinv_p1, 0.3f, bufA, nullptr, bufB);
    hop_kernel<false, true><<<gridHop, TPB>>>(pri_pack, nullptr, pri_rp, pri_cnt,
                                              dinv_p1, 0.3f, bufB, nullptr, z1);

    // z2 sup chain: bufC -> bufA -> bufB
    hop_kernel<false, false><<<gridHop, TPB>>>(sup_pack, nullptr, sup_rp, sup_cnt,
                                               dinv_s, 0.5f, bufC, nullptr, bufA);
    hop_kernel<false, false><<<gridHop, TPB>>>(sup_pack, nullptr, sup_rp, sup_cnt,
                                               dinv_s, 0.5f, bufA, nullptr, bufB);

    // z2 pri chain: bufC -> bufA -> z2 (+ bufB folded into final hop)
    hop_kernel<true, false><<<gridHop, TPB>>>(pri_pack, pri_c2, pri_rp, pri_cnt,
                                              dinv_p2, 0.5f, bufC, nullptr, bufA);
    hop_kernel<true, true><<<gridHop, TPB>>>(pri_pack, pri_c2, pri_rp, pri_cnt,
                                             dinv_p2, 0.5f, bufA, bufB, z2);
}

// round 6
// speedup vs baseline: 2.5638x; 1.2969x over previous
#include <cuda_runtime.h>
#include <cuda_fp16.h>

#define NN 100000
#define EE 1600000
#define FF 128
#define HH 64
#define H2 (HH / 2)      // 32 half2 per row (128 B fp16 rows)

#define SCAN_B 1024
#define NBLK ((NN + SCAN_B - 1) / SCAN_B)   // 98

// ---------------- device scratch (static; no runtime allocation) ------------
__device__ __half2 g_bufA[NN * H2];    // h1
__device__ __half2 g_bufC[NN * H2];    // h2
__device__ __half2 g_bufD1[NN * H2];   // z1 hop1
__device__ __half2 g_bufD2[NN * H2];   // sup hop1
__device__ __half2 g_bufD3[NN * H2];   // pri2 hop1
__device__ __half2 g_bufE[NN * H2];    // sup hop2
__device__ int     g_cnt[2 * NN];      // in-degree: [0,NN) pri, [NN,2NN) sup
__device__ float   g_dinv[3 * NN];     // [0]: pri e=.3, [1]: pri e=.5, [2]: sup e=.5
__device__ int     g_rowptr[2 * NN];   // CSR starts (by col): pri, sup (seg-relative)
__device__ int     g_cursor[2 * NN];
__device__ int     g_bsum[2 * NBLK];
__device__ int4    g_pri_pack[EE];     // {src, bits(dinv_p1[src]), bits(dinv_p2[src]), 0}
__device__ int4    g_sup_pack[EE];     // {src, bits(dinv_s[src]), 0, 0}

// ---------------- degree count --------------------------------------------------
__global__ void count_kernel(const int* __restrict__ pri,
                             const int* __restrict__ sup) {
    int i = blockIdx.x * blockDim.x + threadIdx.x;
    if (i < EE) {
        atomicAdd(&g_cnt[pri[EE + i]], 1);
    } else if (i < 2 * EE) {
        atomicAdd(&g_cnt[NN + sup[i]], 1);
    }
}

// ---------------- scan part 1 (per-block prefix) + fused dinv -------------------
__global__ void scan1_kernel() {   // grid (NBLK, 2), block SCAN_B
    __shared__ int sh[SCAN_B];
    int seg = blockIdx.y;
    int i = blockIdx.x * SCAN_B + threadIdx.x;
    int v = (i < NN) ? g_cnt[seg * NN + i] : 0;

    if (seg == 0 && i < NN) {               // fused dinv computation
        float cp = (float)v;
        float cs = (float)g_cnt[NN + i];
        g_dinv[i]          = rsqrtf(cp + 0.3f);
        g_dinv[NN + i]     = rsqrtf(cp + 0.5f);
        g_dinv[2 * NN + i] = rsqrtf(cs + 0.5f);
    }

    sh[threadIdx.x] = v;
    __syncthreads();
    for (int off = 1; off < SCAN_B; off <<= 1) {
        int t = (threadIdx.x >= off) ? sh[threadIdx.x - off] : 0;
        __syncthreads();
        sh[threadIdx.x] += t;
        __syncthreads();
    }
    if (i < NN) g_rowptr[seg * NN + i] = sh[threadIdx.x] - v;   // exclusive (block-local)
    if (threadIdx.x == SCAN_B - 1) g_bsum[seg * NBLK + blockIdx.x] = sh[threadIdx.x];
}

// ---------------- scan part 2+3 (block offsets + apply + cursor init) -----------
__global__ void scan23_kernel() {  // grid (NBLK, 2), block SCAN_B
    int seg = blockIdx.y;
    int t = threadIdx.x;
    __shared__ int warpsum[32];
    __shared__ int soff;

    int p = (t < NBLK && t < blockIdx.x) ? g_bsum[seg * NBLK + t] : 0;
    for (int o = 16; o; o >>= 1) p += __shfl_down_sync(0xffffffffu, p, o);
    if ((t & 31) == 0) warpsum[t >> 5] = p;
    __syncthreads();
    if (t < 32) {
        int v = warpsum[t];
        for (int o = 16; o; o >>= 1) v += __shfl_down_sync(0xffffffffu, v, o);
        if (t == 0) soff = v;
    }
    __syncthreads();

    int i = blockIdx.x * SCAN_B + t;
    if (i < NN) {
        int rp = g_rowptr[seg * NN + i] + soff;
        g_rowptr[seg * NN + i] = rp;
        g_cursor[seg * NN + i] = rp;
    }
}

// ---------------- fill: counting sort by col, coefs packed ----------------------
__global__ void fill_kernel(const int* __restrict__ pri,
                            const int* __restrict__ sup) {
    int i = blockIdx.x * blockDim.x + threadIdx.x;
    if (i < EE) {
        int r = pri[i], c = pri[EE + i];
        int pos = atomicAdd(&g_cursor[c], 1);
        g_pri_pack[pos] = make_int4(r, __float_as_int(g_dinv[r]),
                                    __float_as_int(g_dinv[NN + r]), 0);
    } else if (i < 2 * EE) {
        int e = i - EE;
        int r = sup[e], c = sup[EE + e];
        int pos = atomicAdd(&g_cursor[NN + c], 1);   // seg-relative, [0,EE)
        g_sup_pack[pos] = make_int4(r, __float_as_int(g_dinv[2 * NN + r]), 0, 0);
    }
}

// ---------------- linear: out = x @ w^T + b, packed f32x2 FFMA ------------------
// one thread per row; 32 packed u64 accumulators; weights pre-packed u64 in smem.
__global__ void linear_kernel(const float* __restrict__ x,
                              const float* __restrict__ w1,
                              const float* __restrict__ b1,
                              const float* __restrict__ w2,
                              const float* __restrict__ b2,
                              __half2* __restrict__ o1,
                              __half2* __restrict__ o2) {
    __shared__ unsigned long long wt2[FF][H2];   // [f][pair] packed (w[2p],w[2p+1]) = 32 KB
    __shared__ float bs[HH];
    const float* w  = blockIdx.y ? w2 : w1;
    const float* b  = blockIdx.y ? b2 : b1;
    __half2* outp   = blockIdx.y ? o2 : o1;

    int tid = threadIdx.x;
    for (int idx = tid; idx < FF * H2; idx += 256) {
        int p = idx & (H2 - 1);
        int f = idx >> 5;
        unsigned long long pk;
        float lo = w[(2 * p) * FF + f];
        float hi = w[(2 * p + 1) * FF + f];
        asm("mov.b64 %0, {%1, %2};" : "=l"(pk) : "f"(lo), "f"(hi));
        wt2[f][p] = pk;
    }
    if (tid < HH) bs[tid] = b[tid];
    __syncthreads();

    int row = blockIdx.x * 256 + tid;
    if (row >= NN) return;

    unsigned long long acc2[H2];
#pragma unroll
    for (int p = 0; p < H2; p++)
        asm("mov.b64 %0, {%1, %2};" : "=l"(acc2[p]) : "f"(bs[2 * p]), "f"(bs[2 * p + 1]));

    const float4* xr = reinterpret_cast<const float4*>(x + (size_t)row * FF);
#pragma unroll 2
    for (int f4 = 0; f4 < FF / 4; f4++) {
        float4 xv = xr[f4];
        float xq[4] = {xv.x, xv.y, xv.z, xv.w};
#pragma unroll
        for (int q = 0; q < 4; q++) {
            int f = f4 * 4 + q;
            unsigned long long xx;
            asm("mov.b64 %0, {%1, %1};" : "=l"(xx) : "f"(xq[q]));
            const ulonglong2* wrow = reinterpret_cast<const ulonglong2*>(&wt2[f][0]);
#pragma unroll
            for (int k8 = 0; k8 < H2 / 2; k8++) {
                ulonglong2 wv = wrow[k8];
                asm("fma.rn.f32x2 %0, %1, %2, %0;" : "+l"(acc2[2 * k8])     : "l"(wv.x), "l"(xx));
                asm("fma.rn.f32x2 %0, %1, %2, %0;" : "+l"(acc2[2 * k8 + 1]) : "l"(wv.y), "l"(xx));
            }
        }
    }

    union { __half2 h2[H2]; uint4 u4[H2 / 4]; } P;
#pragma unroll
    for (int p = 0; p < H2; p++) {
        float lo, hi;
        asm("mov.b64 {%0, %1}, %2;" : "=f"(lo), "=f"(hi) : "l"(acc2[p]));
        P.h2[p] = __floats2half2_rn(lo, hi);
    }
    uint4* op = reinterpret_cast<uint4*>(outp + (size_t)row * H2);
#pragma unroll
    for (int q = 0; q < H2 / 4; q++) op[q] = P.u4[q];
}

// ---------------- fused gather hop: 4 nodes per warp ----------------------------
// out[c,:] = ((1-eps)+eps*dc^2)*h[c,:] + sum dr*dc*h[r,:] (+ add); 8 lanes/node,
// each lane owns 16 B (4 half2) of the 128 B row; gather = 1 LDG.128 per edge.
struct HopArgs {
    const int4*    pack;
    const int*     rowptr;
    const int*     cnt;
    const float*   dinv;
    const __half2* h;
    const __half2* add;     // fp16, folded in when final (may be null)
    void*          out;     // __half2* or float* depending on final
    float          eps;
    int            c2;      // 0: coef = pack.y, 1: coef = pack.z
    int            final_;  // 1: write fp32 to out
};

__global__ void hop_kernel(HopArgs a0, HopArgs a1, HopArgs a2) {
    HopArgs A = (blockIdx.y == 0) ? a0 : ((blockIdx.y == 1) ? a1 : a2);
    int warp = blockIdx.x * (blockDim.x >> 5) + (threadIdx.x >> 5);
    int lane = threadIdx.x & 31;
    int g = lane >> 3;          // node group 0..3
    int i = lane & 7;           // 16-byte slot within row
    int c = warp * 4 + g;       // NN % 4 == 0, grid exact -> c < NN always

    float dc = A.dinv[c];
    float s = (1.0f - A.eps) + A.eps * dc * dc;

    const uint4* hbase = reinterpret_cast<const uint4*>(A.h);
    uint4 hv = hbase[(size_t)c * 8 + i];
    float2 acc[4];
    {
        union { uint4 u; __half2 h2[4]; } U; U.u = hv;
#pragma unroll
        for (int q = 0; q < 4; q++) {
            float2 f = __half22float2(U.h2[q]);
            acc[q].x = s * f.x; acc[q].y = s * f.y;
        }
    }

    int start = A.rowptr[c];
    int n = A.cnt[c];
    int nmax = __reduce_max_sync(0xffffffffu, n);
    int csel = A.c2;

    for (int base = 0; base < nmax; base += 8) {
        int4 e = make_int4(0, 0, 0, 0);
        if (i < n - base) e = A.pack[start + base + i];
        int ecoef = csel ? e.z : e.y;
        int jmax = nmax - base; if (jmax > 8) jmax = 8;
#pragma unroll 2
        for (int j = 0; j < jmax; j++) {
            int   rj = __shfl_sync(0xffffffffu, e.x, j, 8);
            float cf = __int_as_float(__shfl_sync(0xffffffffu, ecoef, j, 8)) * dc;
            uint4 v = hbase[(size_t)rj * 8 + i];
            union { uint4 u; __half2 h2[4]; } U; U.u = v;
#pragma unroll
            for (int q = 0; q < 4; q++) {
                float2 f = __half22float2(U.h2[q]);
                acc[q].x += cf * f.x;
                acc[q].y += cf * f.y;
            }
        }
    }

    if (A.final_) {
        if (A.add) {
            uint4 av = reinterpret_cast<const uint4*>(A.add)[(size_t)c * 8 + i];
            union { uint4 u; __half2 h2[4]; } U; U.u = av;
#pragma unroll
            for (int q = 0; q < 4; q++) {
                float2 f = __half22float2(U.h2[q]);
                acc[q].x += f.x; acc[q].y += f.y;
            }
        }
        float4* op = reinterpret_cast<float4*>((float*)A.out + (size_t)c * HH + i * 8);
        op[0] = make_float4(acc[0].x, acc[0].y, acc[1].x, acc[1].y);
        op[1] = make_float4(acc[2].x, acc[2].y, acc[3].x, acc[3].y);
    } else {
        union { __half2 h2[4]; uint4 u; } P;
#pragma unroll
        for (int q = 0; q < 4; q++) P.h2[q] = __float22half2_rn(acc[q]);
        reinterpret_cast<uint4*>(A.out)[(size_t)c * 8 + i] = P.u;
    }
}

// ---------------- launch --------------------------------------------------------
extern "C" void kernel_launch(void* const* d_in, const int* in_sizes, int n_in,
                              void* d_out, int out_size) {
    const float* x   = (const float*)d_in[0];
    const int*   pri = (const int*)d_in[1];
    const int*   sup = (const int*)d_in[2];
    const float* w1  = (const float*)d_in[3];
    const float* b1  = (const float*)d_in[4];
    const float* w2  = (const float*)d_in[5];
    const float* b2  = (const float*)d_in[6];
    float* out = (float*)d_out;

    __half2 *bufA, *bufC, *bufD1, *bufD2, *bufD3, *bufE;
    float *dinv;
    int *cnt, *rowptr;
    int4 *pri_pack, *sup_pack;
    cudaGetSymbolAddress((void**)&bufA, g_bufA);
    cudaGetSymbolAddress((void**)&bufC, g_bufC);
    cudaGetSymbolAddress((void**)&bufD1, g_bufD1);
    cudaGetSymbolAddress((void**)&bufD2, g_bufD2);
    cudaGetSymbolAddress((void**)&bufD3, g_bufD3);
    cudaGetSymbolAddress((void**)&bufE, g_bufE);
    cudaGetSymbolAddress((void**)&dinv, g_dinv);
    cudaGetSymbolAddress((void**)&cnt, g_cnt);
    cudaGetSymbolAddress((void**)&rowptr, g_rowptr);
    cudaGetSymbolAddress((void**)&pri_pack, g_pri_pack);
    cudaGetSymbolAddress((void**)&sup_pack, g_sup_pack);

    const float* dinv_p1 = dinv;
    const float* dinv_p2 = dinv + NN;
    const float* dinv_s  = dinv + 2 * NN;

    const int TPB = 256;
    const int gridCnt = (2 * EE + TPB - 1) / TPB;

    cudaMemsetAsync(cnt, 0, 2 * NN * sizeof(int));
    count_kernel<<<gridCnt, TPB>>>(pri, sup);
    scan1_kernel<<<dim3(NBLK, 2), SCAN_B>>>();
    scan23_kernel<<<dim3(NBLK, 2), SCAN_B>>>();
    fill_kernel<<<gridCnt, TPB>>>(pri, sup);

    linear_kernel<<<dim3((NN + 255) / 256, 2), 256>>>(x, w1, b1, w2, b2, bufA, bufC);

    float* z1 = out;
    float* z2 = out + (size_t)NN * HH;

    const int gridHopX = NN / 32;   // 4 nodes/warp * 8 warps/block = 32 nodes/block

    HopArgs h_z1a  = {pri_pack, rowptr,      cnt,      dinv_p1, bufA,  nullptr, bufD1, 0.3f, 0, 0};
    HopArgs h_supa = {sup_pack, rowptr + NN, cnt + NN, dinv_s,  bufC,  nullptr, bufD2, 0.5f, 0, 0};
    HopArgs h_p2a  = {pri_pack, rowptr,      cnt,      dinv_p2, bufC,  nullptr, bufD3, 0.5f, 1, 0};

    HopArgs h_z1b  = {pri_pack, rowptr,      cnt,      dinv_p1, bufD1, nullptr, z1,    0.3f, 0, 1};
    HopArgs h_supb = {sup_pack, rowptr + NN, cnt + NN, dinv_s,  bufD2, nullptr, bufE,  0.5f, 0, 0};

    HopArgs h_p2b  = {pri_pack, rowptr,      cnt,      dinv_p2, bufD3, bufE,    z2,    0.5f, 1, 1};

    hop_kernel<<<dim3(gridHopX, 3), TPB>>>(h_z1a, h_supa, h_p2a);
    hop_kernel<<<dim3(gridHopX, 2), TPB>>>(h_z1b, h_supb, h_z1b);
    hop_kernel<<<dim3(gridHopX, 1), TPB>>>(h_p2b, h_p2b, h_p2b);
}

// round 7
// speedup vs baseline: 2.6592x; 1.0372x over previous
#include <cuda_runtime.h>
#include <cuda_fp16.h>

#define NN 100000
#define EE 1600000
#define FF 128
#define HH 64
#define H2 (HH / 2)      // 32 half2 per row (128 B fp16 rows)

#define SCAN_B 1024
#define NBLK ((NN + SCAN_B - 1) / SCAN_B)   // 98

// ---------------- device scratch (static; no runtime allocation) ------------
__device__ __half2 g_bufA[NN * H2];    // h1; later: pri-z2 partial (P2 out)
__device__ __half2 g_bufC[NN * H2];    // h2; later: sup final partial E (P2 out)
__device__ __half2 g_bufD1[NN * H2];   // z1 hop1
__device__ __half2 g_bufD2[NN * H2];   // sup hop1
__device__ __half2 g_bufD3[NN * H2];   // pri2 hop1
__device__ int     g_cnt[2 * NN];      // in-degree: [0,NN) pri, [NN,2NN) sup
__device__ float   g_dinv[3 * NN];     // [0]: pri e=.3, [1]: pri e=.5, [2]: sup e=.5
__device__ int     g_rowptr[2 * NN];   // CSR starts (by col): pri, sup (seg-relative)
__device__ int     g_cursor[2 * NN];
__device__ int     g_bsum[2 * NBLK];
__device__ int4    g_pri_pack[EE];     // {src, bits(dinv_p1[src]), bits(dinv_p2[src]), 0}
__device__ int2    g_sup_pack[EE];     // {src, bits(dinv_s[src])}

// ---------------- degree count --------------------------------------------------
__global__ void count_kernel(const int* __restrict__ pri,
                             const int* __restrict__ sup) {
    int i = blockIdx.x * blockDim.x + threadIdx.x;
    if (i < EE) {
        atomicAdd(&g_cnt[pri[EE + i]], 1);
    } else if (i < 2 * EE) {
        atomicAdd(&g_cnt[NN + sup[i]], 1);
    }
}

// ---------------- scan part 1 (per-block prefix) + fused dinv -------------------
__global__ void scan1_kernel() {   // grid (NBLK, 2), block SCAN_B
    __shared__ int sh[SCAN_B];
    int seg = blockIdx.y;
    int i = blockIdx.x * SCAN_B + threadIdx.x;
    int v = (i < NN) ? g_cnt[seg * NN + i] : 0;

    if (seg == 0 && i < NN) {               // fused dinv computation
        float cp = (float)v;
        float cs = (float)g_cnt[NN + i];
        g_dinv[i]          = rsqrtf(cp + 0.3f);
        g_dinv[NN + i]     = rsqrtf(cp + 0.5f);
        g_dinv[2 * NN + i] = rsqrtf(cs + 0.5f);
    }

    sh[threadIdx.x] = v;
    __syncthreads();
    for (int off = 1; off < SCAN_B; off <<= 1) {
        int t = (threadIdx.x >= off) ? sh[threadIdx.x - off] : 0;
        __syncthreads();
        sh[threadIdx.x] += t;
        __syncthreads();
    }
    if (i < NN) g_rowptr[seg * NN + i] = sh[threadIdx.x] - v;   // exclusive (block-local)
    if (threadIdx.x == SCAN_B - 1) g_bsum[seg * NBLK + blockIdx.x] = sh[threadIdx.x];
}

// ---------------- scan part 2+3 (block offsets + apply + cursor init) -----------
__global__ void scan23_kernel() {  // grid (NBLK, 2), block SCAN_B
    int seg = blockIdx.y;
    int t = threadIdx.x;
    __shared__ int warpsum[32];
    __shared__ int soff;

    int p = (t < NBLK && t < blockIdx.x) ? g_bsum[seg * NBLK + t] : 0;
    for (int o = 16; o; o >>= 1) p += __shfl_down_sync(0xffffffffu, p, o);
    if ((t & 31) == 0) warpsum[t >> 5] = p;
    __syncthreads();
    if (t < 32) {
        int v = warpsum[t];
        for (int o = 16; o; o >>= 1) v += __shfl_down_sync(0xffffffffu, v, o);
        if (t == 0) soff = v;
    }
    __syncthreads();

    int i = blockIdx.x * SCAN_B + t;
    if (i < NN) {
        int rp = g_rowptr[seg * NN + i] + soff;
        g_rowptr[seg * NN + i] = rp;
        g_cursor[seg * NN + i] = rp;
    }
}

// ---------------- fill: counting sort by col, coefs packed ----------------------
__global__ void fill_kernel(const int* __restrict__ pri,
                            const int* __restrict__ sup) {
    int i = blockIdx.x * blockDim.x + threadIdx.x;
    if (i < EE) {
        int r = pri[i], c = pri[EE + i];
        int pos = atomicAdd(&g_cursor[c], 1);
        g_pri_pack[pos] = make_int4(r, __float_as_int(g_dinv[r]),
                                    __float_as_int(g_dinv[NN + r]), 0);
    } else if (i < 2 * EE) {
        int e = i - EE;
        int r = sup[e], c = sup[EE + e];
        int pos = atomicAdd(&g_cursor[NN + c], 1);   // seg-relative, [0,EE)
        g_sup_pack[pos] = make_int2(r, __float_as_int(g_dinv[2 * NN + r]));
    }
}

// ---------------- linear: out = x @ w^T + b, packed f32x2 FFMA ------------------
__global__ void linear_kernel(const float* __restrict__ x,
                              const float* __restrict__ w1,
                              const float* __restrict__ b1,
                              const float* __restrict__ w2,
                              const float* __restrict__ b2,
                              __half2* __restrict__ o1,
                              __half2* __restrict__ o2) {
    __shared__ unsigned long long wt2[FF][H2];   // [f][pair] packed = 32 KB
    __shared__ float bs[HH];
    const float* w  = blockIdx.y ? w2 : w1;
    const float* b  = blockIdx.y ? b2 : b1;
    __half2* outp   = blockIdx.y ? o2 : o1;

    int tid = threadIdx.x;
    for (int idx = tid; idx < FF * H2; idx += 256) {
        int p = idx & (H2 - 1);
        int f = idx >> 5;
        unsigned long long pk;
        float lo = w[(2 * p) * FF + f];
        float hi = w[(2 * p + 1) * FF + f];
        asm("mov.b64 %0, {%1, %2};" : "=l"(pk) : "f"(lo), "f"(hi));
        wt2[f][p] = pk;
    }
    if (tid < HH) bs[tid] = b[tid];
    __syncthreads();

    int row = blockIdx.x * 256 + tid;
    if (row >= NN) return;

    unsigned long long acc2[H2];
#pragma unroll
    for (int p = 0; p < H2; p++)
        asm("mov.b64 %0, {%1, %2};" : "=l"(acc2[p]) : "f"(bs[2 * p]), "f"(bs[2 * p + 1]));

    const float4* xr = reinterpret_cast<const float4*>(x + (size_t)row * FF);
#pragma unroll 2
    for (int f4 = 0; f4 < FF / 4; f4++) {
        float4 xv = xr[f4];
        float xq[4] = {xv.x, xv.y, xv.z, xv.w};
#pragma unroll
        for (int q = 0; q < 4; q++) {
            int f = f4 * 4 + q;
            unsigned long long xx;
            asm("mov.b64 %0, {%1, %1};" : "=l"(xx) : "f"(xq[q]));
            const ulonglong2* wrow = reinterpret_cast<const ulonglong2*>(&wt2[f][0]);
#pragma unroll
            for (int k8 = 0; k8 < H2 / 2; k8++) {
                ulonglong2 wv = wrow[k8];
                asm("fma.rn.f32x2 %0, %1, %2, %0;" : "+l"(acc2[2 * k8])     : "l"(wv.x), "l"(xx));
                asm("fma.rn.f32x2 %0, %1, %2, %0;" : "+l"(acc2[2 * k8 + 1]) : "l"(wv.y), "l"(xx));
            }
        }
    }

    union { __half2 h2[H2]; uint4 u4[H2 / 4]; } P;
#pragma unroll
    for (int p = 0; p < H2; p++) {
        float lo, hi;
        asm("mov.b64 {%0, %1}, %2;" : "=f"(lo), "=f"(hi) : "l"(acc2[p]));
        P.h2[p] = __floats2half2_rn(lo, hi);
    }
    uint4* op = reinterpret_cast<uint4*>(outp + (size_t)row * H2);
#pragma unroll
    for (int q = 0; q < H2 / 4; q++) op[q] = P.u4[q];
}

// ---------------- hop kernels ---------------------------------------------------
// 4 nodes/warp, 8 lanes/node, lane owns 16 B (4 half2) of the 128 B row.
struct FusedArgs {        // pri graph: two chains per edge visit
    const int4* pack;     // {src, c1bits, c2bits, 0}
    const int*  rowptr;
    const int*  cnt;
    const float* dinvA;   // eps=0.3 chain (z1)
    const float* dinvC;   // eps=0.5 chain (z2-pri)
    const uint4* hA;
    const uint4* hC;
    void*  outA;          // fp16 uint4*, or fp32 rows when finalA
    uint4* outC;          // fp16 always
    int finalA;
};
struct SupArgs {          // sup graph, single chain
    const int2* pack;     // {src, cbits}
    const int*  rowptr;
    const int*  cnt;
    const float* dinv;
    const uint4* h;
    uint4* out;           // fp16
};

__device__ __forceinline__ void acc_row(float2 (&acc)[4], uint4 v, float cf) {
    union { uint4 u; __half2 h2[4]; } U; U.u = v;
#pragma unroll
    for (int q = 0; q < 4; q++) {
        float2 f = __half22float2(U.h2[q]);
        acc[q].x += cf * f.x;
        acc[q].y += cf * f.y;
    }
}

__device__ __forceinline__ void hop_fused(const FusedArgs A) {
    int warp = blockIdx.x * (blockDim.x >> 5) + (threadIdx.x >> 5);
    int lane = threadIdx.x & 31;
    int g = lane >> 3, i = lane & 7;
    int c = warp * 4 + g;

    float dcA = A.dinvA[c], dcC = A.dinvC[c];
    float sA = 0.7f + 0.3f * dcA * dcA;
    float sC = 0.5f + 0.5f * dcC * dcC;

    float2 accA[4], accC[4];
    {
        union { uint4 u; __half2 h2[4]; } UA, UC;
        UA.u = A.hA[(size_t)c * 8 + i];
        UC.u = A.hC[(size_t)c * 8 + i];
#pragma unroll
        for (int q = 0; q < 4; q++) {
            float2 fa = __half22float2(UA.h2[q]);
            float2 fc = __half22float2(UC.h2[q]);
            accA[q].x = sA * fa.x; accA[q].y = sA * fa.y;
            accC[q].x = sC * fc.x; accC[q].y = sC * fc.y;
        }
    }

    int start = A.rowptr[c];
    int n = A.cnt[c];
    int nmax = __reduce_max_sync(0xffffffffu, n);

    for (int base = 0; base < nmax; base += 8) {
        int4 e = make_int4(0, 0, 0, 0);
        if (i < n - base) e = A.pack[start + base + i];
        int jmax = nmax - base;
        if (jmax >= 8) {
#pragma unroll
            for (int j = 0; j < 8; j++) {
                int   rj  = __shfl_sync(0xffffffffu, e.x, j, 8);
                float cf1 = __int_as_float(__shfl_sync(0xffffffffu, e.y, j, 8)) * dcA;
                float cf2 = __int_as_float(__shfl_sync(0xffffffffu, e.z, j, 8)) * dcC;
                uint4 vA = A.hA[(size_t)rj * 8 + i];
                uint4 vC = A.hC[(size_t)rj * 8 + i];
                acc_row(accA, vA, cf1);
                acc_row(accC, vC, cf2);
            }
        } else {
            for (int j = 0; j < jmax; j++) {
                int   rj  = __shfl_sync(0xffffffffu, e.x, j, 8);
                float cf1 = __int_as_float(__shfl_sync(0xffffffffu, e.y, j, 8)) * dcA;
                float cf2 = __int_as_float(__shfl_sync(0xffffffffu, e.z, j, 8)) * dcC;
                uint4 vA = A.hA[(size_t)rj * 8 + i];
                uint4 vC = A.hC[(size_t)rj * 8 + i];
                acc_row(accA, vA, cf1);
                acc_row(accC, vC, cf2);
            }
        }
    }

    if (A.finalA) {   // z1 fp32
        float4* op = reinterpret_cast<float4*>((float*)A.outA + (size_t)c * HH + i * 8);
        op[0] = make_float4(accA[0].x, accA[0].y, accA[1].x, accA[1].y);
        op[1] = make_float4(accA[2].x, accA[2].y, accA[3].x, accA[3].y);
    } else {
        union { __half2 h2[4]; uint4 u; } P;
#pragma unroll
        for (int q = 0; q < 4; q++) P.h2[q] = __float22half2_rn(accA[q]);
        reinterpret_cast<uint4*>(A.outA)[(size_t)c * 8 + i] = P.u;
    }
    {
        union { __half2 h2[4]; uint4 u; } P;
#pragma unroll
        for (int q = 0; q < 4; q++) P.h2[q] = __float22half2_rn(accC[q]);
        A.outC[(size_t)c * 8 + i] = P.u;
    }
}

__device__ __forceinline__ void hop_sup(const SupArgs A) {
    int warp = blockIdx.x * (blockDim.x >> 5) + (threadIdx.x >> 5);
    int lane = threadIdx.x & 31;
    int g = lane >> 3, i = lane & 7;
    int c = warp * 4 + g;

    float dc = A.dinv[c];
    float s = 0.5f + 0.5f * dc * dc;

    float2 acc[4];
    {
        union { uint4 u; __half2 h2[4]; } U;
        U.u = A.h[(size_t)c * 8 + i];
#pragma unroll
        for (int q = 0; q < 4; q++) {
            float2 f = __half22float2(U.h2[q]);
            acc[q].x = s * f.x; acc[q].y = s * f.y;
        }
    }

    int start = A.rowptr[c];
    int n = A.cnt[c];
    int nmax = __reduce_max_sync(0xffffffffu, n);

    for (int base = 0; base < nmax; base += 8) {
        int2 e = make_int2(0, 0);
        if (i < n - base) e = A.pack[start + base + i];
        int jmax = nmax - base;
        if (jmax >= 8) {
#pragma unroll
            for (int j = 0; j < 8; j++) {
                int   rj = __shfl_sync(0xffffffffu, e.x, j, 8);
                float cf = __int_as_float(__shfl_sync(0xffffffffu, e.y, j, 8)) * dc;
                uint4 v = A.h[(size_t)rj * 8 + i];
                acc_row(acc, v, cf);
            }
        } else {
            for (int j = 0; j < jmax; j++) {
                int   rj = __shfl_sync(0xffffffffu, e.x, j, 8);
                float cf = __int_as_float(__shfl_sync(0xffffffffu, e.y, j, 8)) * dc;
                uint4 v = A.h[(size_t)rj * 8 + i];
                acc_row(acc, v, cf);
            }
        }
    }

    union { __half2 h2[4]; uint4 u; } P;
#pragma unroll
    for (int q = 0; q < 4; q++) P.h2[q] = __float22half2_rn(acc[q]);
    A.out[(size_t)c * 8 + i] = P.u;
}

__global__ void hop_kernel(FusedArgs fa, SupArgs sa) {
    if (blockIdx.y == 0) hop_fused(fa);
    else                 hop_sup(sa);
}

// ---------------- final add: z2 = pri_part + sup_part (fp16 -> fp32) ------------
__global__ void add_kernel(const uint4* __restrict__ p,
                           const uint4* __restrict__ q,
                           float4* __restrict__ z2) {
    int i = blockIdx.x * blockDim.x + threadIdx.x;
    if (i >= NN * 8) return;
    union { uint4 u; __half2 h2[4]; } UP, UQ;
    UP.u = p[i]; UQ.u = q[i];
    float4 o0, o1;
    float2 a0 = __half22float2(UP.h2[0]), b0 = __half22float2(UQ.h2[0]);
    float2 a1 = __half22float2(UP.h2[1]), b1 = __half22float2(UQ.h2[1]);
    float2 a2 = __half22float2(UP.h2[2]), b2 = __half22float2(UQ.h2[2]);
    float2 a3 = __half22float2(UP.h2[3]), b3 = __half22float2(UQ.h2[3]);
    o0 = make_float4(a0.x + b0.x, a0.y + b0.y, a1.x + b1.x, a1.y + b1.y);
    o1 = make_float4(a2.x + b2.x, a2.y + b2.y, a3.x + b3.x, a3.y + b3.y);
    z2[(size_t)i * 2]     = o0;
    z2[(size_t)i * 2 + 1] = o1;
}

// ---------------- launch --------------------------------------------------------
extern "C" void kernel_launch(void* const* d_in, const int* in_sizes, int n_in,
                              void* d_out, int out_size) {
    const float* x   = (const float*)d_in[0];
    const int*   pri = (const int*)d_in[1];
    const int*   sup = (const int*)d_in[2];
    const float* w1  = (const float*)d_in[3];
    const float* b1  = (const float*)d_in[4];
    const float* w2  = (const float*)d_in[5];
    const float* b2  = (const float*)d_in[6];
    float* out = (float*)d_out;

    __half2 *bufA, *bufC, *bufD1, *bufD2, *bufD3;
    float *dinv;
    int *cnt, *rowptr;
    int4 *pri_pack;
    int2 *sup_pack;
    cudaGetSymbolAddress((void**)&bufA, g_bufA);
    cudaGetSymbolAddress((void**)&bufC, g_bufC);
    cudaGetSymbolAddress((void**)&bufD1, g_bufD1);
    cudaGetSymbolAddress((void**)&bufD2, g_bufD2);
    cudaGetSymbolAddress((void**)&bufD3, g_bufD3);
    cudaGetSymbolAddress((void**)&dinv, g_dinv);
    cudaGetSymbolAddress((void**)&cnt, g_cnt);
    cudaGetSymbolAddress((void**)&rowptr, g_rowptr);
    cudaGetSymbolAddress((void**)&pri_pack, g_pri_pack);
    cudaGetSymbolAddress((void**)&sup_pack, g_sup_pack);

    const float* dinv_p1 = dinv;
    const float* dinv_p2 = dinv + NN;
    const float* dinv_s  = dinv + 2 * NN;

    const int TPB = 256;
    const int gridCnt = (2 * EE + TPB - 1) / TPB;

    cudaMemsetAsync(cnt, 0, 2 * NN * sizeof(int));
    count_kernel<<<gridCnt, TPB>>>(pri, sup);
    scan1_kernel<<<dim3(NBLK, 2), SCAN_B>>>();
    scan23_kernel<<<dim3(NBLK, 2), SCAN_B>>>();
    fill_kernel<<<gridCnt, TPB>>>(pri, sup);

    linear_kernel<<<dim3((NN + 255) / 256, 2), 256>>>(x, w1, b1, w2, b2, bufA, bufC);

    float* z1 = out;
    float* z2 = out + (size_t)NN * HH;

    const int gridHopX = NN / 32;   // 4 nodes/warp * 8 warps/block

    // P1: fused pri hop1 (bufA,bufC -> D1,D3) || sup hop1 (bufC -> D2)
    FusedArgs f1 = {pri_pack, rowptr, cnt, dinv_p1, dinv_p2,
                    (const uint4*)bufA, (const uint4*)bufC,
                    (void*)bufD1, (uint4*)bufD3, 0};
    SupArgs   s1 = {sup_pack, rowptr + NN, cnt + NN, dinv_s,
                    (const uint4*)bufC, (uint4*)bufD2};
    hop_kernel<<<dim3(gridHopX, 2), TPB>>>(f1, s1);

    // P2: fused pri hop2 (D1,D3 -> z1 fp32, bufA fp16) || sup hop2 (D2 -> bufC)
    FusedArgs f2 = {pri_pack, rowptr, cnt, dinv_p1, dinv_p2,
                    (const uint4*)bufD1, (const uint4*)bufD3,
                    (void*)z1, (uint4*)bufA, 1};
    SupArgs   s2 = {sup_pack, rowptr + NN, cnt + NN, dinv_s,
                    (const uint4*)bufD2, (uint4*)bufC};
    hop_kernel<<<dim3(gridHopX, 2), TPB>>>(f2, s2);

    // P3: z2 = bufA + bufC (fp16+fp16 -> fp32)
    add_kernel<<<(NN * 8 + TPB - 1) / TPB, TPB>>>((const uint4*)bufA,
                                                  (const uint4*)bufC,
                                                  (float4*)z2);
}